// round 15
// baseline (speedup 1.0000x reference)
#include <cuda_runtime.h>
#include <math.h>
#include <stdint.h>

typedef unsigned long long u64;

#define T_STEPS 1024
#define BATCH   64
#define DIM     512
#define G3      1536
#define NCTA    128
#define GRPSZ   64            // CTAs per independent barrier group
#define TPB     256
#define PTPB    128
#define RPC     32            // rows per CTA
#define UPCC    8             // units per CTA
#define CHK     256           // k-floats per chunk (2 chunks cover DIM)
#define WKS     512           // floats per weight column
#define NCOLS   (UPCC * 9)    // 72 weight columns per CTA

// ---------------- device scratch ----------------
__device__ float g_xg0[(size_t)T_STEPS * G3 * BATCH];   // [t][g][b]
__device__ float g_h0[2][BATCH * DIM];
__device__ float g_h1[2][BATCH * DIM];
__device__ unsigned g_count[2];
__device__ unsigned g_gen[2];

#define FMA2(acc, a, b) \
    asm("fma.rn.f32x2 %0, %1, %2, %3;" : "=l"(acc) : "l"(a), "l"(b), "l"(acc))

__device__ __forceinline__ float sum2(u64 v) {
    return __uint_as_float((unsigned)v) + __uint_as_float((unsigned)(v >> 32));
}
__device__ __forceinline__ float sigf(float x) { return 1.f / (1.f + expf(-x)); }

// cp.async 16B
__device__ __forceinline__ void cpa16(uint32_t dst, const float* src) {
    asm volatile("cp.async.cg.shared.global [%0], [%1], 16;" :: "r"(dst), "l"(src) : "memory");
}
#define CP_COMMIT() asm volatile("cp.async.commit_group;" ::: "memory")
#define CP_WAIT0()  asm volatile("cp.async.wait_group 0;" ::: "memory")

// ---------------- per-group grid barrier (64 CTAs each) ----------------
__device__ __forceinline__ void gbar(int grp, unsigned target) {
    __syncthreads();
    if (threadIdx.x == 0) {
        unsigned arrived;
        asm volatile("atom.acq_rel.gpu.global.add.u32 %0, [%1], 1;"
                     : "=r"(arrived) : "l"(&g_count[grp]) : "memory");
        if (arrived == GRPSZ - 1) {
            g_count[grp] = 0;
            asm volatile("red.release.gpu.global.add.u32 [%0], 1;"
                         :: "l"(&g_gen[grp]) : "memory");
        } else {
            unsigned g;
            do {
                asm volatile("ld.acquire.gpu.global.u32 %0, [%1];"
                             : "=r"(g) : "l"(&g_gen[grp]) : "memory");
            } while (g < target);
        }
    }
    __syncthreads();
}

// ---------------- phase 1: XG0[t][g][b] = x @ W0 + bi0  (FMA2, 8x4 tile) ------
__global__ void __launch_bounds__(PTPB) precompute_xg0(const float* __restrict__ x,
                                                       const float* __restrict__ W0,
                                                       const float* __restrict__ b0) {
    __shared__ __align__(16) float  xs[32 * 68];    // [k][b]
    __shared__ __align__(16) float2 wsd[32 * 66];   // [k][c] duplicated {w,w}

    const int t     = blockIdx.y;
    const int gbase = blockIdx.x * 64;
    const int tid   = threadIdx.x;

    if (blockIdx.x == 0 && blockIdx.y == 0) {      // per-replay state reset
        if (tid == 0) { g_count[0] = 0; g_count[1] = 0; g_gen[0] = 0; g_gen[1] = 0; }
        for (int j = tid; j < BATCH * DIM; j += PTPB) {
            g_h0[1][j] = 0.0f;
            g_h1[0][j] = 0.0f;
            g_h1[1][j] = 0.0f;
        }
    }

    const int tr = tid >> 4;        // 0..7 -> 8 rows (4 rowpairs)
    const int tc = tid & 15;        // 0..15 -> 4 cols

    u64 acc[4][4] = {};             // [rowpair][col]

    for (int kc = 0; kc < DIM; kc += 32) {
#pragma unroll
        for (int j = 0; j < 16; ++j) {
            int lin = tid + j * PTPB;                 // 0..2047
            int bb = lin >> 5, klx = lin & 31;
            xs[klx * 68 + bb] =
                x[(size_t)bb * (T_STEPS * DIM) + (size_t)t * DIM + kc + klx];
            int kk = lin >> 6, cc = lin & 63;
            float w = W0[(size_t)(kc + kk) * G3 + gbase + cc];
            wsd[kk * 66 + cc] = make_float2(w, w);
        }
        __syncthreads();
        const u64* xp = (const u64*)xs;
        const ulonglong2* wp = (const ulonglong2*)wsd;
#pragma unroll
        for (int kk = 0; kk < 32; ++kk) {
            ulonglong2 w01 = wp[kk * 33 + tc * 2];
            ulonglong2 w23 = wp[kk * 33 + tc * 2 + 1];
#pragma unroll
            for (int p = 0; p < 4; ++p) {
                u64 a = xp[kk * 34 + tr * 4 + p];
                FMA2(acc[p][0], a, w01.x); FMA2(acc[p][1], a, w01.y);
                FMA2(acc[p][2], a, w23.x); FMA2(acc[p][3], a, w23.y);
            }
        }
        __syncthreads();
    }

    float4 bias = *(const float4*)&b0[gbase + tc * 4];
    float bi[4] = {bias.x, bias.y, bias.z, bias.w};
#pragma unroll
    for (int p = 0; p < 4; ++p) {
#pragma unroll
        for (int i = 0; i < 4; ++i) {
            float2 v;
            v.x = __uint_as_float((unsigned)acc[p][i]) + bi[i];
            v.y = __uint_as_float((unsigned)(acc[p][i] >> 32)) + bi[i];
            size_t o = ((size_t)t * G3 + gbase + tc * 4 + i) * BATCH + tr * 8 + 2 * p;
            *(float2*)&g_xg0[o] = v;
        }
    }
}

// ---------------- phase 2: persistent loop, two-phase, 2x256k chunks ----------
// CTA = 8 units x 32 rows; grp = bid&1 selects row half (independent barrier).
// warp = unit cg; lane: rgi = lane>>3 (0..3), kid = lane&7 (k-split 8).
// Cols per unit: j 0-2 = U0 z/r/h, 3-5 = W1 z/r/h (h0-based); 6-8 = U1 (h1).
// Phase A: h0 chunks, 6 cols, accA[48]; Phase B: h1 chunks, 3 cols, accB[24].
#define SMEM_FLOATS (NCOLS * WKS + 2 * RPC * CHK + 128)
#define SMEM_BYTES  (SMEM_FLOATS * 4)

__global__ void __launch_bounds__(TPB, 1)
gru_loop(const float* __restrict__ U0, const float* __restrict__ W1,
         const float* __restrict__ U1, const float* __restrict__ b0,
         const float* __restrict__ b1, float* __restrict__ out) {
    extern __shared__ __align__(16) float sm[];
    float* ws  = sm;                                  // [72][512]
    float* hbf[2] = { sm + NCOLS * WKS,               // 32 x 256 each
                      sm + NCOLS * WKS + RPC * CHK };
    float* bsm = sm + NCOLS * WKS + 2 * RPC * CHK;    // 72+ bias floats
    const uint32_t hbu[2] = { (uint32_t)__cvta_generic_to_shared(hbf[0]),
                              (uint32_t)__cvta_generic_to_shared(hbf[1]) };

    const int tid   = threadIdx.x;
    const int lane  = tid & 31;
    const int cg    = tid >> 5;                // warp = unit 0..7
    const int rgi   = lane >> 3;               // rowgroup 0..3
    const int kid   = lane & 7;                // k-split id
    const int grp   = blockIdx.x & 1;
    const int ubase = (blockIdx.x >> 1) * UPCC;
    const int rbase = grp * RPC;
    const int ug    = ubase + cg;
    const int row   = rbase + rgi * 8 + kid;

    // weights: col c = cg*9 + j (j 0-2 U0, 3-5 W1, 6-8 U1)
    for (int idx = tid; idx < NCOLS * DIM; idx += TPB) {
        int c = idx >> 9, k = idx & 511;
        int uu = c / 9, j = c % 9;
        const float* mat = (j < 3) ? U0 : (j < 6 ? W1 : U1);
        int gate = (j < 3) ? j : (j < 6 ? j - 3 : j - 6);
        ws[c * WKS + k] = __ldg(mat + (size_t)k * G3 + gate * 512 + ubase + uu);
    }
    // biases into smem: [unit][9] = br0 z/r/h, bi1 z/r/h, br1 z/r/h
    if (tid < 24) {
        int uu = tid / 3, g = tid % 3;
        bsm[uu * 9 + g]     = b0[G3 + g * 512 + ubase + uu];
        bsm[uu * 9 + 3 + g] = b1[g * 512 + ubase + uu];
        bsm[uu * 9 + 6 + g] = b1[G3 + g * 512 + ubase + uu];
    }
    __syncthreads();

    const float* wbase = ws + (size_t)cg * 9 * WKS;
    unsigned gen = 0;

    for (int t = 0; t <= T_STEPS; ++t) {
        const float* h0in  = g_h0[(t + 1) & 1];   // h0(t-1)
        const float* h1in  = g_h1[(t + 1) & 1];   // h1(t-2)
        float*       h0out = g_h0[t & 1];
        float*       h1out = g_h1[t & 1];

        // stage A0 (h0, chunk 0 -> buf0): 8 x 16B per thread
#pragma unroll
        for (int j = 0; j < 8; ++j) {
            int idx = tid + j * TPB;             // 0..2047
            int rr = idx >> 6, k4 = idx & 63;
            cpa16(hbu[0] + (uint32_t)(rr * CHK + k4 * 4) * 4u,
                  h0in + (rbase + rr) * 512 + k4 * 4);
        }
        CP_COMMIT();

        // gate prefetch
        float xz = 0.f, xr = 0.f, xh = 0.f, h0o = 0.f, h1o = 0.f;
        if (t < T_STEPS) {
            size_t xb = ((size_t)t * G3 + ug) * BATCH + row;
            xz  = __ldg(&g_xg0[xb]);
            xr  = __ldg(&g_xg0[xb + 512 * BATCH]);
            xh  = __ldg(&g_xg0[xb + 1024 * BATCH]);
            h0o = __ldcg(h0in + row * 512 + ug);
        }
        if (t >= 1) h1o = __ldcg(h1in + row * 512 + ug);

        CP_WAIT0(); __syncthreads();

        // stage A1 (h0, chunk 1 -> buf1)
#pragma unroll
        for (int j = 0; j < 8; ++j) {
            int idx = tid + j * TPB;
            int rr = idx >> 6, k4 = idx & 63;
            cpa16(hbu[1] + (uint32_t)(rr * CHK + k4 * 4) * 4u,
                  h0in + (rbase + rr) * 512 + CHK + k4 * 4);
        }
        CP_COMMIT();

        u64 accA[48] = {};   // [r*6 + j]
        // dots A chunk 0
        {
            const float* hc = hbf[0] + rgi * 8 * CHK;
            const float* wk = wbase;
#pragma unroll
            for (int it = 0; it < 8; ++it) {
                int ko = (it * 8 + kid) * 4;
                ulonglong2 W[6];
#pragma unroll
                for (int j = 0; j < 6; ++j) W[j] = *(const ulonglong2*)(wk + j * WKS + ko);
#pragma unroll
                for (int r = 0; r < 8; ++r) {
                    ulonglong2 hv = *(const ulonglong2*)(hc + r * CHK + ko);
#pragma unroll
                    for (int j = 0; j < 6; ++j) {
                        FMA2(accA[r * 6 + j], hv.x, W[j].x);
                        FMA2(accA[r * 6 + j], hv.y, W[j].y);
                    }
                }
            }
        }
        CP_WAIT0(); __syncthreads();     // A1 ready; buf0 free

        // stage B0 (h1, chunk 0 -> buf0)
#pragma unroll
        for (int j = 0; j < 8; ++j) {
            int idx = tid + j * TPB;
            int rr = idx >> 6, k4 = idx & 63;
            cpa16(hbu[0] + (uint32_t)(rr * CHK + k4 * 4) * 4u,
                  h1in + (rbase + rr) * 512 + k4 * 4);
        }
        CP_COMMIT();

        // dots A chunk 1
        {
            const float* hc = hbf[1] + rgi * 8 * CHK;
            const float* wk = wbase + CHK;
#pragma unroll
            for (int it = 0; it < 8; ++it) {
                int ko = (it * 8 + kid) * 4;
                ulonglong2 W[6];
#pragma unroll
                for (int j = 0; j < 6; ++j) W[j] = *(const ulonglong2*)(wk + j * WKS + ko);
#pragma unroll
                for (int r = 0; r < 8; ++r) {
                    ulonglong2 hv = *(const ulonglong2*)(hc + r * CHK + ko);
#pragma unroll
                    for (int j = 0; j < 6; ++j) {
                        FMA2(accA[r * 6 + j], hv.x, W[j].x);
                        FMA2(accA[r * 6 + j], hv.y, W[j].y);
                    }
                }
            }
        }
        CP_WAIT0(); __syncthreads();     // B0 ready; buf1 free

        // stage B1 (h1, chunk 1 -> buf1)
#pragma unroll
        for (int j = 0; j < 8; ++j) {
            int idx = tid + j * TPB;
            int rr = idx >> 6, k4 = idx & 63;
            cpa16(hbu[1] + (uint32_t)(rr * CHK + k4 * 4) * 4u,
                  h1in + (rbase + rr) * 512 + CHK + k4 * 4);
        }
        CP_COMMIT();

        // reduce A (progressive halving: 84 shfl) — overlaps B1 staging
        float sA[6];
        {
            float v8[8][6];
#pragma unroll
            for (int r = 0; r < 8; ++r)
#pragma unroll
                for (int j = 0; j < 6; ++j) v8[r][j] = sum2(accA[r * 6 + j]);
#pragma unroll
            for (int r = 0; r < 8; ++r)
#pragma unroll
                for (int j = 0; j < 6; ++j)
                    v8[r][j] += __shfl_xor_sync(0xffffffffu, v8[r][j], 1);
            float v4[4][6];
#pragma unroll
            for (int i = 0; i < 4; ++i)
#pragma unroll
                for (int j = 0; j < 6; ++j)
                    v4[i][j] = (kid & 1) ? v8[2 * i + 1][j] : v8[2 * i][j];
#pragma unroll
            for (int i = 0; i < 4; ++i)
#pragma unroll
                for (int j = 0; j < 6; ++j)
                    v4[i][j] += __shfl_xor_sync(0xffffffffu, v4[i][j], 2);
            float v2[2][6];
#pragma unroll
            for (int i = 0; i < 2; ++i)
#pragma unroll
                for (int j = 0; j < 6; ++j)
                    v2[i][j] = (kid & 2) ? v4[2 * i + 1][j] : v4[2 * i][j];
#pragma unroll
            for (int i = 0; i < 2; ++i)
#pragma unroll
                for (int j = 0; j < 6; ++j)
                    v2[i][j] += __shfl_xor_sync(0xffffffffu, v2[i][j], 4);
#pragma unroll
            for (int j = 0; j < 6; ++j)
                sA[j] = (kid & 4) ? v2[1][j] : v2[0][j];
        }

        u64 accB[24] = {};   // [r*3 + j]
        // dots B chunk 0 (buf0 ready from earlier wait)
        {
            const float* hc = hbf[0] + rgi * 8 * CHK;
            const float* wk = wbase + 6 * WKS;
#pragma unroll
            for (int it = 0; it < 8; ++it) {
                int ko = (it * 8 + kid) * 4;
                ulonglong2 W[3];
#pragma unroll
                for (int j = 0; j < 3; ++j) W[j] = *(const ulonglong2*)(wk + j * WKS + ko);
#pragma unroll
                for (int r = 0; r < 8; ++r) {
                    ulonglong2 hv = *(const ulonglong2*)(hc + r * CHK + ko);
#pragma unroll
                    for (int j = 0; j < 3; ++j) {
                        FMA2(accB[r * 3 + j], hv.x, W[j].x);
                        FMA2(accB[r * 3 + j], hv.y, W[j].y);
                    }
                }
            }
        }
        CP_WAIT0(); __syncthreads();     // B1 ready

        // dots B chunk 1
        {
            const float* hc = hbf[1] + rgi * 8 * CHK;
            const float* wk = wbase + 6 * WKS + CHK;
#pragma unroll
            for (int it = 0; it < 8; ++it) {
                int ko = (it * 8 + kid) * 4;
                ulonglong2 W[3];
#pragma unroll
                for (int j = 0; j < 3; ++j) W[j] = *(const ulonglong2*)(wk + j * WKS + ko);
#pragma unroll
                for (int r = 0; r < 8; ++r) {
                    ulonglong2 hv = *(const ulonglong2*)(hc + r * CHK + ko);
#pragma unroll
                    for (int j = 0; j < 3; ++j) {
                        FMA2(accB[r * 3 + j], hv.x, W[j].x);
                        FMA2(accB[r * 3 + j], hv.y, W[j].y);
                    }
                }
            }
        }

        // reduce B (progressive halving: 42 shfl)
        float sB[3];
        {
            float v8[8][3];
#pragma unroll
            for (int r = 0; r < 8; ++r)
#pragma unroll
                for (int j = 0; j < 3; ++j) v8[r][j] = sum2(accB[r * 3 + j]);
#pragma unroll
            for (int r = 0; r < 8; ++r)
#pragma unroll
                for (int j = 0; j < 3; ++j)
                    v8[r][j] += __shfl_xor_sync(0xffffffffu, v8[r][j], 1);
            float v4[4][3];
#pragma unroll
            for (int i = 0; i < 4; ++i)
#pragma unroll
                for (int j = 0; j < 3; ++j)
                    v4[i][j] = (kid & 1) ? v8[2 * i + 1][j] : v8[2 * i][j];
#pragma unroll
            for (int i = 0; i < 4; ++i)
#pragma unroll
                for (int j = 0; j < 3; ++j)
                    v4[i][j] += __shfl_xor_sync(0xffffffffu, v4[i][j], 2);
            float v2[2][3];
#pragma unroll
            for (int i = 0; i < 2; ++i)
#pragma unroll
                for (int j = 0; j < 3; ++j)
                    v2[i][j] = (kid & 2) ? v4[2 * i + 1][j] : v4[2 * i][j];
#pragma unroll
            for (int i = 0; i < 2; ++i)
#pragma unroll
                for (int j = 0; j < 3; ++j)
                    v2[i][j] += __shfl_xor_sync(0xffffffffu, v2[i][j], 4);
#pragma unroll
            for (int j = 0; j < 3; ++j)
                sB[j] = (kid & 4) ? v2[1][j] : v2[0][j];
        }

        // pointwise (biases from smem broadcast)
        const float* bs = bsm + cg * 9;
        if (t < T_STEPS) {
            float z    = sigf(xz + sA[0] + bs[0]);
            float rgt  = sigf(xr + sA[1] + bs[1]);
            float cand = tanhf(xh + rgt * (sA[2] + bs[2]));
            h0out[row * 512 + ug] = z * h0o + (1.f - z) * cand;
        }
        if (t >= 1) {
            float z1    = sigf(sA[3] + bs[3] + sB[0] + bs[6]);
            float r1    = sigf(sA[4] + bs[4] + sB[1] + bs[7]);
            float cand1 = tanhf(sA[5] + bs[5] + r1 * (sB[2] + bs[8]));
            float h1n   = z1 * h1o + (1.f - z1) * cand1;
            h1out[row * 512 + ug] = h1n;
            if (t == T_STEPS) out[row * 512 + ug] = h1n;
        }

        gbar(grp, ++gen);
    }
}

// ---------------- launcher ----------------
extern "C" void kernel_launch(void* const* d_in, const int* in_sizes, int n_in,
                              void* d_out, int out_size) {
    const float* x  = (const float*)d_in[0];
    const float* W0 = (const float*)d_in[1];
    const float* U0 = (const float*)d_in[2];
    const float* b0 = (const float*)d_in[3];
    const float* W1 = (const float*)d_in[4];
    const float* U1 = (const float*)d_in[5];
    const float* b1 = (const float*)d_in[6];
    float* out = (float*)d_out;

    cudaFuncSetAttribute(gru_loop, cudaFuncAttributeMaxDynamicSharedMemorySize,
                         SMEM_BYTES);

    precompute_xg0<<<dim3(24, 1024), PTPB>>>(x, W0, b0);
    gru_loop<<<NCTA, TPB, SMEM_BYTES>>>(U0, W1, U1, b0, b1, out);
}

// round 17
// speedup vs baseline: 1.0534x; 1.0534x over previous
#include <cuda_runtime.h>
#include <math.h>
#include <stdint.h>

typedef unsigned long long u64;

#define T_STEPS 1024
#define BATCH   64
#define DIM     512
#define G3      1536
#define NCTA    128
#define GRPSZ   64            // CTAs per independent barrier group
#define TPB     256
#define PTPB    256
#define RPC     32            // rows per CTA
#define UPCC    8             // units per CTA
#define CHK     256           // k-floats per chunk (2 chunks cover DIM)
#define WKS     512           // floats per weight column
#define NCOLS   (UPCC * 9)    // 72 weight columns per CTA

// ---------------- device scratch ----------------
__device__ float g_xg0[(size_t)T_STEPS * G3 * BATCH];   // [t][g][b]
__device__ float g_h0[2][BATCH * DIM];
__device__ float g_h1[2][BATCH * DIM];
__device__ unsigned g_count[2];
__device__ unsigned g_gen[2];

#define FMA2(acc, a, b) \
    asm("fma.rn.f32x2 %0, %1, %2, %3;" : "=l"(acc) : "l"(a), "l"(b), "l"(acc))

__device__ __forceinline__ float sum2(u64 v) {
    return __uint_as_float((unsigned)v) + __uint_as_float((unsigned)(v >> 32));
}
__device__ __forceinline__ float sigf(float x) { return 1.f / (1.f + expf(-x)); }

// cp.async 16B
__device__ __forceinline__ void cpa16(uint32_t dst, const float* src) {
    asm volatile("cp.async.cg.shared.global [%0], [%1], 16;" :: "r"(dst), "l"(src) : "memory");
}
#define CP_COMMIT() asm volatile("cp.async.commit_group;" ::: "memory")
#define CP_WAIT0()  asm volatile("cp.async.wait_group 0;" ::: "memory")

// ---------------- per-group grid barrier (64 CTAs each) ----------------
__device__ __forceinline__ void gbar(int grp, unsigned target) {
    __syncthreads();
    if (threadIdx.x == 0) {
        unsigned arrived;
        asm volatile("atom.acq_rel.gpu.global.add.u32 %0, [%1], 1;"
                     : "=r"(arrived) : "l"(&g_count[grp]) : "memory");
        if (arrived == GRPSZ - 1) {
            g_count[grp] = 0;
            asm volatile("red.release.gpu.global.add.u32 [%0], 1;"
                         :: "l"(&g_gen[grp]) : "memory");
        } else {
            unsigned g;
            do {
                asm volatile("ld.acquire.gpu.global.u32 %0, [%1];"
                             : "=r"(g) : "l"(&g_gen[grp]) : "memory");
            } while (g < target);
        }
    }
    __syncthreads();
}

// ---------------- phase 1: XG0[t][g][b] = x @ W0 + bi0  (FMA2, R13 config) ----
__global__ void __launch_bounds__(PTPB) precompute_xg0(const float* __restrict__ x,
                                                       const float* __restrict__ W0,
                                                       const float* __restrict__ b0) {
    __shared__ __align__(16) float  xs[32 * 68];    // [k][b]
    __shared__ __align__(16) float2 wsd[32 * 66];   // [k][c] duplicated {w,w}

    const int t     = blockIdx.y;
    const int gbase = blockIdx.x * 64;
    const int tid   = threadIdx.x;

    if (blockIdx.x == 0 && blockIdx.y == 0) {      // per-replay state reset
        if (tid == 0) { g_count[0] = 0; g_count[1] = 0; g_gen[0] = 0; g_gen[1] = 0; }
        for (int j = tid; j < BATCH * DIM; j += PTPB) {
            g_h0[1][j] = 0.0f;
            g_h1[0][j] = 0.0f;
            g_h1[1][j] = 0.0f;
        }
    }

    const int tr = tid & 15, tc = tid >> 4;
    const int r0 = tr * 4, c0 = tc * 4;

    u64 acc[2][4] = {};

    for (int kc = 0; kc < DIM; kc += 32) {
#pragma unroll
        for (int j = 0; j < 8; ++j) {
            int lin = tid + j * PTPB;
            int bb = lin >> 5, klx = lin & 31;
            xs[klx * 68 + bb] =
                x[(size_t)bb * (T_STEPS * DIM) + (size_t)t * DIM + kc + klx];
            int kk = lin >> 6, cc = lin & 63;
            float w = W0[(size_t)(kc + kk) * G3 + gbase + cc];
            wsd[kk * 66 + cc] = make_float2(w, w);
        }
        __syncthreads();
        const u64* xp = (const u64*)xs;
        const ulonglong2* wp = (const ulonglong2*)wsd;
#pragma unroll
        for (int kk = 0; kk < 32; ++kk) {
            u64 a0 = xp[kk * 34 + tr * 2];
            u64 a1 = xp[kk * 34 + tr * 2 + 1];
            ulonglong2 w01 = wp[kk * 33 + tc * 2];
            ulonglong2 w23 = wp[kk * 33 + tc * 2 + 1];
            FMA2(acc[0][0], a0, w01.x); FMA2(acc[0][1], a0, w01.y);
            FMA2(acc[0][2], a0, w23.x); FMA2(acc[0][3], a0, w23.y);
            FMA2(acc[1][0], a1, w01.x); FMA2(acc[1][1], a1, w01.y);
            FMA2(acc[1][2], a1, w23.x); FMA2(acc[1][3], a1, w23.y);
        }
        __syncthreads();
    }

    float4 bias = *(const float4*)&b0[gbase + c0];
    float bi[4] = {bias.x, bias.y, bias.z, bias.w};
#pragma unroll
    for (int rp = 0; rp < 2; ++rp) {
#pragma unroll
        for (int i = 0; i < 4; ++i) {
            float2 v;
            v.x = __uint_as_float((unsigned)acc[rp][i]) + bi[i];
            v.y = __uint_as_float((unsigned)(acc[rp][i] >> 32)) + bi[i];
            size_t o = ((size_t)t * G3 + gbase + c0 + i) * BATCH + r0 + 2 * rp;
            *(float2*)&g_xg0[o] = v;
        }
    }
}

// ---------------- phase 2: persistent loop (R14 config, best measured) --------
// CTA = 8 units x 32 rows; grp = bid&1 selects row half (independent barrier).
// warp = unit cg; lane: rgi = lane>>3 (0..3), kid = lane&7 (k-split 8).
// Cols per unit: j 0-2 = U0 z/r/h, 3-5 = W1 z/r/h (h0-based); 6-8 = U1 (h1).
// Phase A: h0 chunks, 6 cols, accA[48]; Phase B: h1 chunks, 3 cols, accB[24].
#define SMEM_FLOATS (NCOLS * WKS + 2 * RPC * CHK + 128)
#define SMEM_BYTES  (SMEM_FLOATS * 4)

__global__ void __launch_bounds__(TPB, 1)
gru_loop(const float* __restrict__ U0, const float* __restrict__ W1,
         const float* __restrict__ U1, const float* __restrict__ b0,
         const float* __restrict__ b1, float* __restrict__ out) {
    extern __shared__ __align__(16) float sm[];
    float* ws  = sm;                                  // [72][512]
    float* hbf[2] = { sm + NCOLS * WKS,               // 32 x 256 each
                      sm + NCOLS * WKS + RPC * CHK };
    float* bsm = sm + NCOLS * WKS + 2 * RPC * CHK;    // bias floats
    const uint32_t hbu[2] = { (uint32_t)__cvta_generic_to_shared(hbf[0]),
                              (uint32_t)__cvta_generic_to_shared(hbf[1]) };

    const int tid   = threadIdx.x;
    const int lane  = tid & 31;
    const int cg    = tid >> 5;                // warp = unit 0..7
    const int rgi   = lane >> 3;               // rowgroup 0..3
    const int kid   = lane & 7;                // k-split id
    const int grp   = blockIdx.x & 1;
    const int ubase = (blockIdx.x >> 1) * UPCC;
    const int rbase = grp * RPC;
    const int ug    = ubase + cg;
    const int row   = rbase + rgi * 8 + kid;

    // weights: col c = cg*9 + j (j 0-2 U0, 3-5 W1, 6-8 U1)
    for (int idx = tid; idx < NCOLS * DIM; idx += TPB) {
        int c = idx >> 9, k = idx & 511;
        int uu = c / 9, j = c % 9;
        const float* mat = (j < 3) ? U0 : (j < 6 ? W1 : U1);
        int gate = (j < 3) ? j : (j < 6 ? j - 3 : j - 6);
        ws[c * WKS + k] = __ldg(mat + (size_t)k * G3 + gate * 512 + ubase + uu);
    }
    // biases into smem: [unit][9] = br0 z/r/h, bi1 z/r/h, br1 z/r/h
    if (tid < 24) {
        int uu = tid / 3, g = tid % 3;
        bsm[uu * 9 + g]     = b0[G3 + g * 512 + ubase + uu];
        bsm[uu * 9 + 3 + g] = b1[g * 512 + ubase + uu];
        bsm[uu * 9 + 6 + g] = b1[G3 + g * 512 + ubase + uu];
    }
    __syncthreads();

    const float* wbase = ws + (size_t)cg * 9 * WKS;
    unsigned gen = 0;

    for (int t = 0; t <= T_STEPS; ++t) {
        const float* h0in  = g_h0[(t + 1) & 1];   // h0(t-1)
        const float* h1in  = g_h1[(t + 1) & 1];   // h1(t-2)
        float*       h0out = g_h0[t & 1];
        float*       h1out = g_h1[t & 1];

        // stage A0 (h0, chunk 0 -> buf0): 8 x 16B per thread
#pragma unroll
        for (int j = 0; j < 8; ++j) {
            int idx = tid + j * TPB;             // 0..2047
            int rr = idx >> 6, k4 = idx & 63;
            cpa16(hbu[0] + (uint32_t)(rr * CHK + k4 * 4) * 4u,
                  h0in + (rbase + rr) * 512 + k4 * 4);
        }
        CP_COMMIT();

        // gate prefetch
        float xz = 0.f, xr = 0.f, xh = 0.f, h0o = 0.f, h1o = 0.f;
        if (t < T_STEPS) {
            size_t xb = ((size_t)t * G3 + ug) * BATCH + row;
            xz  = __ldg(&g_xg0[xb]);
            xr  = __ldg(&g_xg0[xb + 512 * BATCH]);
            xh  = __ldg(&g_xg0[xb + 1024 * BATCH]);
            h0o = __ldcg(h0in + row * 512 + ug);
        }
        if (t >= 1) h1o = __ldcg(h1in + row * 512 + ug);

        CP_WAIT0(); __syncthreads();

        // stage A1 (h0, chunk 1 -> buf1)
#pragma unroll
        for (int j = 0; j < 8; ++j) {
            int idx = tid + j * TPB;
            int rr = idx >> 6, k4 = idx & 63;
            cpa16(hbu[1] + (uint32_t)(rr * CHK + k4 * 4) * 4u,
                  h0in + (rbase + rr) * 512 + CHK + k4 * 4);
        }
        CP_COMMIT();

        u64 accA[48] = {};   // [r*6 + j]
        // dots A chunk 0
        {
            const float* hc = hbf[0] + rgi * 8 * CHK;
            const float* wk = wbase;
#pragma unroll
            for (int it = 0; it < 8; ++it) {
                int ko = (it * 8 + kid) * 4;
                ulonglong2 W[6];
#pragma unroll
                for (int j = 0; j < 6; ++j) W[j] = *(const ulonglong2*)(wk + j * WKS + ko);
#pragma unroll
                for (int r = 0; r < 8; ++r) {
                    ulonglong2 hv = *(const ulonglong2*)(hc + r * CHK + ko);
#pragma unroll
                    for (int j = 0; j < 6; ++j) {
                        FMA2(accA[r * 6 + j], hv.x, W[j].x);
                        FMA2(accA[r * 6 + j], hv.y, W[j].y);
                    }
                }
            }
        }
        CP_WAIT0(); __syncthreads();     // A1 ready; buf0 free

        // stage B0 (h1, chunk 0 -> buf0)
#pragma unroll
        for (int j = 0; j < 8; ++j) {
            int idx = tid + j * TPB;
            int rr = idx >> 6, k4 = idx & 63;
            cpa16(hbu[0] + (uint32_t)(rr * CHK + k4 * 4) * 4u,
                  h1in + (rbase + rr) * 512 + k4 * 4);
        }
        CP_COMMIT();

        // dots A chunk 1
        {
            const float* hc = hbf[1] + rgi * 8 * CHK;
            const float* wk = wbase + CHK;
#pragma unroll
            for (int it = 0; it < 8; ++it) {
                int ko = (it * 8 + kid) * 4;
                ulonglong2 W[6];
#pragma unroll
                for (int j = 0; j < 6; ++j) W[j] = *(const ulonglong2*)(wk + j * WKS + ko);
#pragma unroll
                for (int r = 0; r < 8; ++r) {
                    ulonglong2 hv = *(const ulonglong2*)(hc + r * CHK + ko);
#pragma unroll
                    for (int j = 0; j < 6; ++j) {
                        FMA2(accA[r * 6 + j], hv.x, W[j].x);
                        FMA2(accA[r * 6 + j], hv.y, W[j].y);
                    }
                }
            }
        }
        CP_WAIT0(); __syncthreads();     // B0 ready; buf1 free

        // stage B1 (h1, chunk 1 -> buf1)
#pragma unroll
        for (int j = 0; j < 8; ++j) {
            int idx = tid + j * TPB;
            int rr = idx >> 6, k4 = idx & 63;
            cpa16(hbu[1] + (uint32_t)(rr * CHK + k4 * 4) * 4u,
                  h1in + (rbase + rr) * 512 + CHK + k4 * 4);
        }
        CP_COMMIT();

        // reduce A (progressive halving: 84 shfl) — overlaps B1 staging
        float sA[6];
        {
            float v8[8][6];
#pragma unroll
            for (int r = 0; r < 8; ++r)
#pragma unroll
                for (int j = 0; j < 6; ++j) v8[r][j] = sum2(accA[r * 6 + j]);
#pragma unroll
            for (int r = 0; r < 8; ++r)
#pragma unroll
                for (int j = 0; j < 6; ++j)
                    v8[r][j] += __shfl_xor_sync(0xffffffffu, v8[r][j], 1);
            float v4[4][6];
#pragma unroll
            for (int i = 0; i < 4; ++i)
#pragma unroll
                for (int j = 0; j < 6; ++j)
                    v4[i][j] = (kid & 1) ? v8[2 * i + 1][j] : v8[2 * i][j];
#pragma unroll
            for (int i = 0; i < 4; ++i)
#pragma unroll
                for (int j = 0; j < 6; ++j)
                    v4[i][j] += __shfl_xor_sync(0xffffffffu, v4[i][j], 2);
            float v2[2][6];
#pragma unroll
            for (int i = 0; i < 2; ++i)
#pragma unroll
                for (int j = 0; j < 6; ++j)
                    v2[i][j] = (kid & 2) ? v4[2 * i + 1][j] : v4[2 * i][j];
#pragma unroll
            for (int i = 0; i < 2; ++i)
#pragma unroll
                for (int j = 0; j < 6; ++j)
                    v2[i][j] += __shfl_xor_sync(0xffffffffu, v2[i][j], 4);
#pragma unroll
            for (int j = 0; j < 6; ++j)
                sA[j] = (kid & 4) ? v2[1][j] : v2[0][j];
        }

        u64 accB[24] = {};   // [r*3 + j]
        // dots B chunk 0 (buf0 ready from earlier wait)
        {
            const float* hc = hbf[0] + rgi * 8 * CHK;
            const float* wk = wbase + 6 * WKS;
#pragma unroll
            for (int it = 0; it < 8; ++it) {
                int ko = (it * 8 + kid) * 4;
                ulonglong2 W[3];
#pragma unroll
                for (int j = 0; j < 3; ++j) W[j] = *(const ulonglong2*)(wk + j * WKS + ko);
#pragma unroll
                for (int r = 0; r < 8; ++r) {
                    ulonglong2 hv = *(const ulonglong2*)(hc + r * CHK + ko);
#pragma unroll
                    for (int j = 0; j < 3; ++j) {
                        FMA2(accB[r * 3 + j], hv.x, W[j].x);
                        FMA2(accB[r * 3 + j], hv.y, W[j].y);
                    }
                }
            }
        }
        CP_WAIT0(); __syncthreads();     // B1 ready

        // dots B chunk 1
        {
            const float* hc = hbf[1] + rgi * 8 * CHK;
            const float* wk = wbase + 6 * WKS + CHK;
#pragma unroll
            for (int it = 0; it < 8; ++it) {
                int ko = (it * 8 + kid) * 4;
                ulonglong2 W[3];
#pragma unroll
                for (int j = 0; j < 3; ++j) W[j] = *(const ulonglong2*)(wk + j * WKS + ko);
#pragma unroll
                for (int r = 0; r < 8; ++r) {
                    ulonglong2 hv = *(const ulonglong2*)(hc + r * CHK + ko);
#pragma unroll
                    for (int j = 0; j < 3; ++j) {
                        FMA2(accB[r * 3 + j], hv.x, W[j].x);
                        FMA2(accB[r * 3 + j], hv.y, W[j].y);
                    }
                }
            }
        }

        // reduce B (progressive halving: 42 shfl)
        float sB[3];
        {
            float v8[8][3];
#pragma unroll
            for (int r = 0; r < 8; ++r)
#pragma unroll
                for (int j = 0; j < 3; ++j) v8[r][j] = sum2(accB[r * 3 + j]);
#pragma unroll
            for (int r = 0; r < 8; ++r)
#pragma unroll
                for (int j = 0; j < 3; ++j)
                    v8[r][j] += __shfl_xor_sync(0xffffffffu, v8[r][j], 1);
            float v4[4][3];
#pragma unroll
            for (int i = 0; i < 4; ++i)
#pragma unroll
                for (int j = 0; j < 3; ++j)
                    v4[i][j] = (kid & 1) ? v8[2 * i + 1][j] : v8[2 * i][j];
#pragma unroll
            for (int i = 0; i < 4; ++i)
#pragma unroll
                for (int j = 0; j < 3; ++j)
                    v4[i][j] += __shfl_xor_sync(0xffffffffu, v4[i][j], 2);
            float v2[2][3];
#pragma unroll
            for (int i = 0; i < 2; ++i)
#pragma unroll
                for (int j = 0; j < 3; ++j)
                    v2[i][j] = (kid & 2) ? v4[2 * i + 1][j] : v4[2 * i][j];
#pragma unroll
            for (int i = 0; i < 2; ++i)
#pragma unroll
                for (int j = 0; j < 3; ++j)
                    v2[i][j] += __shfl_xor_sync(0xffffffffu, v2[i][j], 4);
#pragma unroll
            for (int j = 0; j < 3; ++j)
                sB[j] = (kid & 4) ? v2[1][j] : v2[0][j];
        }

        // pointwise (biases from smem broadcast)
        const float* bs = bsm + cg * 9;
        if (t < T_STEPS) {
            float z    = sigf(xz + sA[0] + bs[0]);
            float rgt  = sigf(xr + sA[1] + bs[1]);
            float cand = tanhf(xh + rgt * (sA[2] + bs[2]));
            h0out[row * 512 + ug] = z * h0o + (1.f - z) * cand;
        }
        if (t >= 1) {
            float z1    = sigf(sA[3] + bs[3] + sB[0] + bs[6]);
            float r1    = sigf(sA[4] + bs[4] + sB[1] + bs[7]);
            float cand1 = tanhf(sA[5] + bs[5] + r1 * (sB[2] + bs[8]));
            float h1n   = z1 * h1o + (1.f - z1) * cand1;
            h1out[row * 512 + ug] = h1n;
            if (t == T_STEPS) out[row * 512 + ug] = h1n;
        }

        gbar(grp, ++gen);
    }
}

// ---------------- launcher ----------------
extern "C" void kernel_launch(void* const* d_in, const int* in_sizes, int n_in,
                              void* d_out, int out_size) {
    const float* x  = (const float*)d_in[0];
    const float* W0 = (const float*)d_in[1];
    const float* U0 = (const float*)d_in[2];
    const float* b0 = (const float*)d_in[3];
    const float* W1 = (const float*)d_in[4];
    const float* U1 = (const float*)d_in[5];
    const float* b1 = (const float*)d_in[6];
    float* out = (float*)d_out;

    cudaFuncSetAttribute(gru_loop, cudaFuncAttributeMaxDynamicSharedMemorySize,
                         SMEM_BYTES);

    precompute_xg0<<<dim3(24, 1024), PTPB>>>(x, W0, b0);
    gru_loop<<<NCTA, TPB, SMEM_BYTES>>>(U0, W1, U1, b0, b1, out);
}